// round 16
// baseline (speedup 1.0000x reference)
#include <cuda_runtime.h>

#define Bn 128
#define Tn 1024
#define Kn 16
#define CH 32
#define NCHK (Tn/CH)

static __device__ __forceinline__ float ex2f(float x){ float r; asm("ex2.approx.f32 %0, %1;" : "=f"(r) : "f"(x)); return r; }
static __device__ __forceinline__ float lg2f(float x){ float r; asm("lg2.approx.f32 %0, %1;" : "=f"(r) : "f"(x)); return r; }
static __device__ __forceinline__ float rcpf(float x){ float r; asm("rcp.approx.f32 %0, %1;" : "=f"(r) : "f"(x)); return r; }
#define FMA2(d,a,b,c) asm("fma.rn.f32x2 %0, %1, %2, %3;" : "=l"(d) : "l"(a), "l"(b), "l"(c))
#define CBAR() asm volatile("" ::: "memory")

static __device__ __forceinline__ void mwait(unsigned mb, unsigned ph) {
  asm volatile(
    "{\n\t.reg .pred P;\n"
    "W%=:\n\tmbarrier.try_wait.parity.acquire.cta.shared::cta.b64 P, [%0], %1, 0x989680;\n"
    "\t@P bra D%=;\n\tbra W%=;\nD%=:\n\t}"
    :: "r"(mb), "r"(ph) : "memory");
}

struct __align__(16) Sm {
  float  Ls[2][CH][256];      // 64KB double-buffered logits (bulk-async dst)
  float  Gs[2][CH][16];       // 4KB gumbel
  float2 ENL[2][CH][17];      // (en,l) producer->stats, pitch 17 (bank-stagger)
  float  Y  [2][CH][20];      // normalized y, pitch 20 (80B, 16B-aligned rows)
  float  WP [16][16];         // log(transP), stats-private
  float  Epar[16];            // e-vector, parity-interleaved
  unsigned long long mbar[2];
};
#define SMEMSZ (sizeof(Sm))

__global__ void __launch_bounds__(256,1) fused_kernel(
 const float* __restrict__ logits, const float* __restrict__ gum,
 const float* __restrict__ Am, const float* __restrict__ Bmm,
 const float* __restrict__ Cm, const float* __restrict__ trP,
 float* __restrict__ oA, float* __restrict__ oB, float* __restrict__ oC,
 float* __restrict__ oLq, float* __restrict__ oLp)
{
  extern __shared__ char smraw[];
  Sm* sm = (Sm*)smraw;
  const int b = blockIdx.x;
  const int tid = threadIdx.x;
  const int wid = tid >> 5, lane = tid & 31;
  const int h = lane >> 4, j = lane & 15;
  const float LOG2E = 1.4426950408889634f;
  const float LN2   = 0.69314718055994531f;
  const float C2L   = 2.8853900817779268f;   // (1/tau)*log2(e), tau=0.5

  if (wid == 7) {
    // ========== producer: regime scan (SMSP3, top priority; shares SMSP only with 1 mixer) ==========
    const float* Lg = logits + (size_t)b * Tn * 256;
    const float* Gg = gum    + (size_t)b * Tn * 16;
    const unsigned mb0 = (unsigned)__cvta_generic_to_shared(&sm->mbar[0]);
    const unsigned sL  = (unsigned)__cvta_generic_to_shared(&sm->Ls[0][0][0]);
    const unsigned sG  = (unsigned)__cvta_generic_to_shared(&sm->Gs[0][0][0]);
    #define ISSUE_CHUNK(c, bf) do { \
      unsigned _mb = mb0 + (unsigned)(bf)*8u; \
      asm volatile("mbarrier.arrive.expect_tx.shared.b64 _, [%0], %1;" :: "r"(_mb), "r"(34816u) : "memory"); \
      asm volatile("cp.async.bulk.shared::cluster.global.mbarrier::complete_tx::bytes [%0], [%1], %2, [%3];" \
        :: "r"(sL + (unsigned)(bf)*32768u), "l"(Lg + (size_t)(c)*CH*256), "r"(32768u), "r"(_mb) : "memory"); \
      asm volatile("cp.async.bulk.shared::cluster.global.mbarrier::complete_tx::bytes [%0], [%1], %2, [%3];" \
        :: "r"(sG + (unsigned)(bf)*2048u), "l"(Gg + (size_t)(c)*CH*16), "r"(2048u), "r"(_mb) : "memory"); \
    } while(0)
    if (lane == 0) {
      asm volatile("mbarrier.init.shared.b64 [%0], 1;" :: "r"(mb0)    : "memory");
      asm volatile("mbarrier.init.shared.b64 [%0], 1;" :: "r"(mb0+8u) : "memory");
      asm volatile("fence.proxy.async.shared::cta;" ::: "memory");
      ISSUE_CHUNK(0, 0);
      ISSUE_CHUNK(1, 1);
    }
    __syncwarp();
    // E16: full e-vector, parity-interleaved ([0..7]=even k, [8..15]=odd k); ekh = this half's 8
    float E16[16], ekh[8];
    #pragma unroll
    for (int k = 0; k < 16; ++k) E16[k] = 1.0f;
    #pragma unroll
    for (int m = 0; m < 8; ++m) ekh[m] = 1.0f;
    const float* EparH = &sm->Epar[h*8];     // register-offset base for this half's e's
    for (int c = 0; c < NCHK + 2; ++c) {
      if (c < NCHK) {
        const int bf = c & 1;
        mwait(mb0 + (unsigned)bf*8u, (unsigned)((c >> 1) & 1));
        const float* Lsb = &sm->Ls[bf][0][0];
        const float* Gsb = &sm->Gs[bf][0][0];
        float2* ENLb = &sm->ENL[bf][0][0];
        #pragma unroll 4
        for (int i = 0; i < CH; ++i) {
          float Lc[8];
          #pragma unroll
          for (int m = 0; m < 8; ++m) Lc[m] = Lsb[i*256 + (2*m + h)*16 + j];  // conflict-free
          float gz = Gsb[i*16 + j] * C2L;
          // S from full local e-vector (parallel with the u shfl — not serialized behind it)
          float S = (((E16[0]+E16[1])+(E16[2]+E16[3]))+((E16[4]+E16[5])+(E16[6]+E16[7])))
                  + (((E16[8]+E16[9])+(E16[10]+E16[11]))+((E16[12]+E16[13])+(E16[14]+E16[15])));
          float r  = rcpf(S);
          float rC = r * C2L;
          float p[8];
          #pragma unroll
          for (int m = 0; m < 8; ++m) p[m] = ekh[m] * Lc[m];
          float pu = ((p[0]+p[1])+(p[2]+p[3])) + ((p[4]+p[5])+(p[6]+p[7]));
          float u  = pu + __shfl_xor_sync(0xffffffffu, pu, 16);   // combine parities
          float en = ex2f(fmaf(u, rC, gz));  // exp((l+g)/tau)
          float l  = u * r;
          if (lane < Kn) {
            sm->Epar[(j & 1)*8 + (j >> 1)] = en;   // parity-interleaved
            ENLb[i*17 + j] = make_float2(en, l);
          }
          CBAR();
          float4 ea = *(const float4*)&sm->Epar[0];
          float4 eb = *(const float4*)&sm->Epar[4];
          float4 ec = *(const float4*)&sm->Epar[8];
          float4 ed = *(const float4*)&sm->Epar[12];
          float4 k0 = *(const float4*)&EparH[0];
          float4 k1 = *(const float4*)&EparH[4];
          CBAR();
          E16[0]=ea.x; E16[1]=ea.y; E16[2]=ea.z; E16[3]=ea.w;
          E16[4]=eb.x; E16[5]=eb.y; E16[6]=eb.z; E16[7]=eb.w;
          E16[8]=ec.x; E16[9]=ec.y; E16[10]=ec.z; E16[11]=ec.w;
          E16[12]=ed.x; E16[13]=ed.y; E16[14]=ed.z; E16[15]=ed.w;
          ekh[0]=k0.x; ekh[1]=k0.y; ekh[2]=k0.z; ekh[3]=k0.w;
          ekh[4]=k1.x; ekh[5]=k1.y; ekh[6]=k1.z; ekh[7]=k1.w;
        }
        if (c + 2 < NCHK && lane == 0) ISSUE_CHUNK(c + 2, bf);
      }
      __syncthreads();
    }
    #undef ISSUE_CHUNK
  } else if (wid == 6) {
    // ========== stats (SMSP2): in-thread, ZERO shuffles. lane = timestep within chunk ==========
    for (int e = lane; e < 256; e += 32) sm->WP[0][e] = lg2f(trP[e]) * LN2;  // log transP
    if (lane < 16) sm->Y[1][CH-1][lane] = 1.0f/16.0f;   // t=-1 carry (only feeds overridden lp[0])
    const int t = lane;
    for (int c = 0; c < NCHK + 2; ++c) {
      if (c >= 1 && c <= NCHK) {
        const int sc = c - 1, sbuf = sc & 1;
        const float2* er = &sm->ENL[sbuf][t][0];
        float en[16], l[16];
        #pragma unroll
        for (int k = 0; k < 16; ++k) { float2 v = er[k]; en[k] = v.x; l[k] = v.y; }
        float Se = 0.f;
        #pragma unroll
        for (int k = 0; k < 16; ++k) Se += en[k];
        float r = rcpf(Se);
        float y[16];
        #pragma unroll
        for (int k = 0; k < 16; ++k) { y[k] = en[k] * r; sm->Y[sbuf][t][k] = y[k]; }
        CBAR();                                         // converged warp: STS before LDS below
        const float* yp = (t > 0) ? &sm->Y[sbuf][t-1][0] : &sm->Y[sbuf^1][CH-1][0];
        float sel = 0.f, syl = 0.f;
        #pragma unroll
        for (int k = 0; k < 16; ++k) { sel += ex2f(l[k]*LOG2E); syl = fmaf(y[k], l[k], syl); }
        float lq = syl - lg2f(sel)*LN2;                 // sum y*(l - lse(l))
        float acc = 0.f;
        #pragma unroll
        for (int i = 0; i < 16; ++i) {                  // yprev^T logP y
          const float4* wr = (const float4*)&sm->WP[i][0];   // uniform -> broadcast
          float4 w0 = wr[0], w1 = wr[1], w2 = wr[2], w3 = wr[3];
          float z = w0.x*y[0];
          z = fmaf(w0.y,y[1], z); z = fmaf(w0.z,y[2], z); z = fmaf(w0.w,y[3], z);
          z = fmaf(w1.x,y[4], z); z = fmaf(w1.y,y[5], z); z = fmaf(w1.z,y[6], z); z = fmaf(w1.w,y[7], z);
          z = fmaf(w2.x,y[8], z); z = fmaf(w2.y,y[9], z); z = fmaf(w2.z,y[10],z); z = fmaf(w2.w,y[11],z);
          z = fmaf(w3.x,y[12],z); z = fmaf(w3.y,y[13],z); z = fmaf(w3.z,y[14],z); z = fmaf(w3.w,y[15],z);
          acc = fmaf(yp[i], z, acc);
        }
        const int gt = sc*CH + t;
        float lp = (gt == 0) ? -2.7725887222397811f : acc;   // t=0: -log K
        oLq[(size_t)b*Tn + gt] = lq;                    // 32 consecutive floats: coalesced
        oLp[(size_t)b*Tn + gt] = lp;
      }
      __syncthreads();
    }
  } else {
    // ========== mixers (wid 0-5; SMSP0:{0,4} SMSP1:{1,5} SMSP2:{2} SMSP3:{3}) ==========
    const int q  = wid*32 + lane;                     // 0..191
    const int g  = q / 96;                            // alternate timesteps
    const int gq = q % 96;
    const int cols = gq * 4;
    const bool isA = cols < 256;
    unsigned long long cc0[Kn], cc1[Kn];
    #pragma unroll
    for (int k = 0; k < Kn; ++k) {
      float a,bb,cx,d;
      if (isA) { const float* s = Am + k*256 + cols;       a=s[0]; bb=s[1]; cx=s[2]; d=s[3]; }
      else     { const float* s = Bmm + k*128 + (cols-256); a=s[0]; bb=s[1]; cx=s[2]; d=s[3]; }
      asm("mov.b64 %0, {%1,%2};" : "=l"(cc0[k]) : "f"(a),  "f"(bb));
      asm("mov.b64 %0, {%1,%2};" : "=l"(cc1[k]) : "f"(cx), "f"(d));
    }
    for (int c = 0; c < NCHK + 2; ++c) {
      if (c >= 2) {
        const int mc = c - 2, mbuf = mc & 1;
        const size_t tbase = (size_t)b * Tn + mc*CH;
        #pragma unroll 2
        for (int ii = 0; ii < 16; ++ii) {
          const int tt = 2*ii + g;
          const float4* yr = (const float4*)&sm->Y[mbuf][tt][0];  // uniform row: broadcast
          float4 v0 = yr[0], v1 = yr[1], v2 = yr[2], v3 = yr[3];
          unsigned long long yy[Kn];
          asm("mov.b64 %0, {%1,%1};" : "=l"(yy[0])  : "f"(v0.x));
          asm("mov.b64 %0, {%1,%1};" : "=l"(yy[1])  : "f"(v0.y));
          asm("mov.b64 %0, {%1,%1};" : "=l"(yy[2])  : "f"(v0.z));
          asm("mov.b64 %0, {%1,%1};" : "=l"(yy[3])  : "f"(v0.w));
          asm("mov.b64 %0, {%1,%1};" : "=l"(yy[4])  : "f"(v1.x));
          asm("mov.b64 %0, {%1,%1};" : "=l"(yy[5])  : "f"(v1.y));
          asm("mov.b64 %0, {%1,%1};" : "=l"(yy[6])  : "f"(v1.z));
          asm("mov.b64 %0, {%1,%1};" : "=l"(yy[7])  : "f"(v1.w));
          asm("mov.b64 %0, {%1,%1};" : "=l"(yy[8])  : "f"(v2.x));
          asm("mov.b64 %0, {%1,%1};" : "=l"(yy[9])  : "f"(v2.y));
          asm("mov.b64 %0, {%1,%1};" : "=l"(yy[10]) : "f"(v2.z));
          asm("mov.b64 %0, {%1,%1};" : "=l"(yy[11]) : "f"(v2.w));
          asm("mov.b64 %0, {%1,%1};" : "=l"(yy[12]) : "f"(v3.x));
          asm("mov.b64 %0, {%1,%1};" : "=l"(yy[13]) : "f"(v3.y));
          asm("mov.b64 %0, {%1,%1};" : "=l"(yy[14]) : "f"(v3.z));
          asm("mov.b64 %0, {%1,%1};" : "=l"(yy[15]) : "f"(v3.w));
          unsigned long long a01 = 0ull, a23 = 0ull;
          #pragma unroll
          for (int k = 0; k < Kn; ++k) { FMA2(a01, yy[k], cc0[k], a01); FMA2(a23, yy[k], cc1[k], a23); }
          unsigned r0,r1,r2,r3;
          asm("mov.b64 {%0,%1}, %2;" : "=r"(r0), "=r"(r1) : "l"(a01));
          asm("mov.b64 {%0,%1}, %2;" : "=r"(r2), "=r"(r3) : "l"(a23));
          float4 v = make_float4(__uint_as_float(r0), __uint_as_float(r1),
                                 __uint_as_float(r2), __uint_as_float(r3));
          const size_t t = tbase + tt;
          if (isA) *(float4*)(oA + t*256 + cols) = v;
          else     *(float4*)(oB + t*128 + (cols - 256)) = v;
        }
      }
      __syncthreads();
    }
  }
  // C_seq: per-batch copy of Cm (512 floats)
  if (tid < 128)
    ((float4*)(oC + (size_t)b*512))[tid] = ((const float4*)Cm)[tid];
}

extern "C" void kernel_launch(void* const* d_in, const int* in_sizes, int n_in,
                              void* d_out, int out_size) {
  const float* logits = (const float*)d_in[0];
  const float* gum    = (const float*)d_in[1];
  const float* Am     = (const float*)d_in[2];
  const float* Bmm    = (const float*)d_in[3];
  const float* Cm     = (const float*)d_in[4];
  const float* trP    = (const float*)d_in[5];
  float* out = (float*)d_out;
  // output layout: A_seq | B_seq | C_seq | log_qseq | log_pseq
  float* oA  = out;                               // 128*1024*256
  float* oB  = out + 33554432ull;                 // 128*1024*128
  float* oC  = out + 50331648ull;                 // 128*512
  float* oLq = out + 50397184ull;                 // 128*1024
  float* oLp = out + 50528256ull;                 // 128*1024
  static bool smem_ok = []() {
    cudaFuncSetAttribute(fused_kernel, cudaFuncAttributeMaxDynamicSharedMemorySize, (int)SMEMSZ);
    return true;
  }();
  (void)smem_ok;
  fused_kernel<<<Bn, 256, SMEMSZ>>>(logits, gum, Am, Bmm, Cm, trP, oA, oB, oC, oLq, oLp);
}

// round 17
// speedup vs baseline: 1.2623x; 1.2623x over previous
#include <cuda_runtime.h>

#define Bn 128
#define Tn 1024
#define Kn 16
#define CH 32
#define NCHK (Tn/CH)

static __device__ __forceinline__ float ex2f(float x){ float r; asm("ex2.approx.f32 %0, %1;" : "=f"(r) : "f"(x)); return r; }
static __device__ __forceinline__ float lg2f(float x){ float r; asm("lg2.approx.f32 %0, %1;" : "=f"(r) : "f"(x)); return r; }
static __device__ __forceinline__ float rcpf(float x){ float r; asm("rcp.approx.f32 %0, %1;" : "=f"(r) : "f"(x)); return r; }
#define FMA2(d,a,b,c) asm("fma.rn.f32x2 %0, %1, %2, %3;" : "=l"(d) : "l"(a), "l"(b), "l"(c))
#define CBAR() asm volatile("" ::: "memory")

static __device__ __forceinline__ void mwait(unsigned mb, unsigned ph) {
  asm volatile(
    "{\n\t.reg .pred P;\n"
    "W%=:\n\tmbarrier.try_wait.parity.acquire.cta.shared::cta.b64 P, [%0], %1, 0x989680;\n"
    "\t@P bra D%=;\n\tbra W%=;\nD%=:\n\t}"
    :: "r"(mb), "r"(ph) : "memory");
}

struct __align__(16) Sm {
  float  Ls[2][CH][256];      // 64KB double-buffered logits (bulk-async dst)
  float  Gs[2][CH][16];       // 4KB gumbel
  float2 ENL[2][CH][16];      // 8KB (en, l) per step, producer -> stats
  float2 YYd[2][CH][16];      // 8KB (y, y) pairs, stats -> mixers
  float  Epar[16];            // e-vector, parity-interleaved
  unsigned long long mbar[2];
};
#define SMEMSZ (sizeof(Sm))

__global__ void __launch_bounds__(256,1) fused_kernel(
 const float* __restrict__ logits, const float* __restrict__ gum,
 const float* __restrict__ Am, const float* __restrict__ Bmm,
 const float* __restrict__ Cm, const float* __restrict__ trP,
 float* __restrict__ oA, float* __restrict__ oB, float* __restrict__ oC,
 float* __restrict__ oLq, float* __restrict__ oLp)
{
  extern __shared__ char smraw[];
  Sm* sm = (Sm*)smraw;
  const int b = blockIdx.x;
  const int tid = threadIdx.x;
  const int wid = tid >> 5, lane = tid & 31;
  const int h = lane >> 4, j = lane & 15;
  const float LOG2E = 1.4426950408889634f;
  const float LN2   = 0.69314718055994531f;
  const float C2L   = 2.8853900817779268f;   // (1/tau)*log2(e), tau=0.5

  if (wid == 7) {
    // ========== producer: sequential regime scan (SMSP3; shares only with light mixer w3) ==========
    const float* Lg = logits + (size_t)b * Tn * 256;
    const float* Gg = gum    + (size_t)b * Tn * 16;
    const unsigned mb0 = (unsigned)__cvta_generic_to_shared(&sm->mbar[0]);
    const unsigned sL  = (unsigned)__cvta_generic_to_shared(&sm->Ls[0][0][0]);
    const unsigned sG  = (unsigned)__cvta_generic_to_shared(&sm->Gs[0][0][0]);
    #define ISSUE_CHUNK(c, bf) do { \
      unsigned _mb = mb0 + (unsigned)(bf)*8u; \
      asm volatile("mbarrier.arrive.expect_tx.shared.b64 _, [%0], %1;" :: "r"(_mb), "r"(34816u) : "memory"); \
      asm volatile("cp.async.bulk.shared::cluster.global.mbarrier::complete_tx::bytes [%0], [%1], %2, [%3];" \
        :: "r"(sL + (unsigned)(bf)*32768u), "l"(Lg + (size_t)(c)*CH*256), "r"(32768u), "r"(_mb) : "memory"); \
      asm volatile("cp.async.bulk.shared::cluster.global.mbarrier::complete_tx::bytes [%0], [%1], %2, [%3];" \
        :: "r"(sG + (unsigned)(bf)*2048u), "l"(Gg + (size_t)(c)*CH*16), "r"(2048u), "r"(_mb) : "memory"); \
    } while(0)
    if (lane == 0) {
      asm volatile("mbarrier.init.shared.b64 [%0], 1;" :: "r"(mb0)    : "memory");
      asm volatile("mbarrier.init.shared.b64 [%0], 1;" :: "r"(mb0+8u) : "memory");
      asm volatile("fence.proxy.async.shared::cta;" ::: "memory");
      ISSUE_CHUNK(0, 0);
      ISSUE_CHUNK(1, 1);
    }
    __syncwarp();
    float ekh[8];
    #pragma unroll
    for (int m = 0; m < 8; ++m) ekh[m] = 1.0f;       // e=1 <=> uniform y0
    for (int c = 0; c < NCHK + 2; ++c) {
      if (c < NCHK) {
        const int bf = c & 1;
        mwait(mb0 + (unsigned)bf*8u, (unsigned)((c >> 1) & 1));
        const float* Lsb = &sm->Ls[bf][0][0];
        const float* Gsb = &sm->Gs[bf][0][0];
        #pragma unroll 8
        for (int i = 0; i < CH; ++i) {
          float Lc[8];
          #pragma unroll
          for (int m = 0; m < 8; ++m) Lc[m] = Lsb[i*256 + (2*m + h)*16 + j];
          float gz = Gsb[i*16 + j] * C2L;
          float p[8];
          #pragma unroll
          for (int m = 0; m < 8; ++m) p[m] = ekh[m] * Lc[m];
          float pu = ((p[0]+p[1])+(p[2]+p[3])) + ((p[4]+p[5])+(p[6]+p[7]));
          float pS = ((ekh[0]+ekh[1])+(ekh[2]+ekh[3])) + ((ekh[4]+ekh[5])+(ekh[6]+ekh[7]));
          float u = pu + __shfl_xor_sync(0xffffffffu, pu, 16);   // combine parities
          float S = pS + __shfl_xor_sync(0xffffffffu, pS, 16);
          float r  = rcpf(S);
          float en = ex2f(fmaf(u, r * C2L, gz));     // exp((l+g)/tau)
          float l  = u * r;
          if (lane < Kn) {
            sm->Epar[(j & 1)*8 + (j >> 1)] = en;     // parity-interleaved
            sm->ENL[bf][i][j] = make_float2(en, l);
          }
          CBAR();
          float4 ea = *(const float4*)&sm->Epar[h*8];
          float4 eb = *(const float4*)&sm->Epar[h*8 + 4];
          CBAR();
          ekh[0]=ea.x; ekh[1]=ea.y; ekh[2]=ea.z; ekh[3]=ea.w;
          ekh[4]=eb.x; ekh[5]=eb.y; ekh[6]=eb.z; ekh[7]=eb.w;
        }
        if (c + 2 < NCHK && lane == 0) ISSUE_CHUNK(c + 2, bf);
      }
      __syncthreads();
    }
    #undef ISSUE_CHUNK
  } else if (wid == 6) {
    // ========== stats: normalize + lq/lp, chunk c-1 (SMSP2, away from producer) ==========
    float logPc[Kn];
    #pragma unroll
    for (int k = 0; k < Kn; ++k) logPc[k] = lg2f(trP[k*Kn + j]) * LN2;
    if (lane < Kn) sm->YYd[1][CH-1][j] = make_float2(1.0f/16.0f, 1.0f/16.0f); // t=-1 carry
    for (int c = 0; c < NCHK + 2; ++c) {
      if (c >= 1 && c <= NCHK) {
        const int sc = c - 1, sbuf = sc & 1;
        #pragma unroll 2
        for (int ii = 0; ii < 16; ++ii) {
          const int t = 2*ii + h;
          const int gt = sc*CH + t;
          float2 v = sm->ENL[sbuf][t][j];
          float en = v.x, l = v.y;
          float Se = en;
          #pragma unroll
          for (int d = 8; d; d >>= 1) Se += __shfl_xor_sync(0xffffffffu, Se, d);
          float y = en * rcpf(Se);
          sm->YYd[sbuf][t][j] = make_float2(y, y);
          CBAR();
          const int tm = t - 1;
          const float2* ypr = (tm >= 0) ? &sm->YYd[sbuf][tm][0] : &sm->YYd[sbuf^1][CH-1][0];
          float wr = 0.f;
          #pragma unroll
          for (int k = 0; k < Kn; ++k) wr = fmaf(ypr[k].x, logPc[k], wr);
          float sel = ex2f(l * LOG2E), syl = y * l, slp = y * wr;
          #pragma unroll
          for (int d = 8; d; d >>= 1) {
            sel += __shfl_xor_sync(0xffffffffu, sel, d);
            syl += __shfl_xor_sync(0xffffffffu, syl, d);
            slp += __shfl_xor_sync(0xffffffffu, slp, d);
          }
          float lq = syl - lg2f(sel) * LN2;
          float lp = (gt == 0) ? -2.7725887222397811f : slp;   // t=0: -log K
          if (j == 0) {
            oLq[(size_t)b*Tn + gt] = lq;
            oLp[(size_t)b*Tn + gt] = lp;
          }
        }
      }
      __syncthreads();
    }
  } else {
    // ========== mixers (wid 0-5): A_seq/B_seq for chunk c-2 ==========
    // SMSP0:{w0,w4} SMSP1:{w1,w5} SMSP2:{w2}+stats SMSP3:{w3}+producer
    const int q  = wid*32 + lane;                    // 0..191
    const int g  = q / 96;                           // alternate timesteps
    const int gq = q % 96;
    const int cols = gq * 4;
    const bool isA = cols < 256;
    unsigned long long cc0[Kn], cc1[Kn];
    #pragma unroll
    for (int k = 0; k < Kn; ++k) {
      float a,bb,cx,d;
      if (isA) { const float* s = Am + k*256 + cols;       a=s[0]; bb=s[1]; cx=s[2]; d=s[3]; }
      else     { const float* s = Bmm + k*128 + (cols-256); a=s[0]; bb=s[1]; cx=s[2]; d=s[3]; }
      asm("mov.b64 %0, {%1,%2};" : "=l"(cc0[k]) : "f"(a),  "f"(bb));
      asm("mov.b64 %0, {%1,%2};" : "=l"(cc1[k]) : "f"(cx), "f"(d));
    }
    for (int c = 0; c < NCHK + 2; ++c) {
      if (c >= 2) {
        const int mc = c - 2, mbuf = mc & 1;
        const size_t tbase = (size_t)b * Tn + mc*CH;
        #pragma unroll 2
        for (int ii = 0; ii < 16; ++ii) {
          const int tt = 2*ii + g;
          const ulonglong2* yr = (const ulonglong2*)&sm->YYd[mbuf][tt][0];
          unsigned long long yy[Kn];
          #pragma unroll
          for (int qq = 0; qq < 8; ++qq) { ulonglong2 w = yr[qq]; yy[2*qq] = w.x; yy[2*qq+1] = w.y; }
          unsigned long long a01 = 0ull, a23 = 0ull;
          #pragma unroll
          for (int k = 0; k < Kn; ++k) { FMA2(a01, yy[k], cc0[k], a01); FMA2(a23, yy[k], cc1[k], a23); }
          unsigned r0,r1,r2,r3;
          asm("mov.b64 {%0,%1}, %2;" : "=r"(r0), "=r"(r1) : "l"(a01));
          asm("mov.b64 {%0,%1}, %2;" : "=r"(r2), "=r"(r3) : "l"(a23));
          float4 v = make_float4(__uint_as_float(r0), __uint_as_float(r1),
                                 __uint_as_float(r2), __uint_as_float(r3));
          const size_t t = tbase + tt;
          if (isA) *(float4*)(oA + t*256 + cols) = v;
          else     *(float4*)(oB + t*128 + (cols - 256)) = v;
        }
      }
      __syncthreads();
    }
  }
  // C_seq: per-batch copy of Cm (512 floats)
  if (tid < 128)
    ((float4*)(oC + (size_t)b*512))[tid] = ((const float4*)Cm)[tid];
}

extern "C" void kernel_launch(void* const* d_in, const int* in_sizes, int n_in,
                              void* d_out, int out_size) {
  const float* logits = (const float*)d_in[0];
  const float* gum    = (const float*)d_in[1];
  const float* Am     = (const float*)d_in[2];
  const float* Bmm    = (const float*)d_in[3];
  const float* Cm     = (const float*)d_in[4];
  const float* trP    = (const float*)d_in[5];
  float* out = (float*)d_out;
  // output layout: A_seq | B_seq | C_seq | log_qseq | log_pseq
  float* oA  = out;                               // 128*1024*256
  float* oB  = out + 33554432ull;                 // 128*1024*128
  float* oC  = out + 50331648ull;                 // 128*512
  float* oLq = out + 50397184ull;                 // 128*1024
  float* oLp = out + 50528256ull;                 // 128*1024
  static bool smem_ok = []() {
    cudaFuncSetAttribute(fused_kernel, cudaFuncAttributeMaxDynamicSharedMemorySize, (int)SMEMSZ);
    return true;
  }();
  (void)smem_ok;
  fused_kernel<<<Bn, 256, SMEMSZ>>>(logits, gum, Am, Bmm, Cm, trP, oA, oB, oC, oLq, oLp);
}